// round 2
// baseline (speedup 1.0000x reference)
#include <cuda_runtime.h>

// PANLoss fused single-kernel version.
// Inputs (metadata order):
//   0 pred_regions (16,1,640,640) f32   1 regions_gt f32
//   2 pred_kernels f32                  3 kernels_gt f32
//   4 pred_similarities (16,4,640,640) f32
//   5 text labels (16,640,640) i32 [0,8]   6 kernel labels i32 [0,8]
// Output: 5 f32 scalars.

#define HW4   102400
#define NB    16
#define BPB   72
#define NTH   256
#define NSEG  9
#define NBIN  81
#define EPSF  1e-5f
#define NPXF  409600.0f
#define CNT_BIT (1ULL << 40)
#define S2_MASK (CNT_BIT - 1ULL)
#define S2_SCALE 256.0f
#define INV_S2_SCALE (1.0f/256.0f)

__device__ unsigned long long g_hist[NB * NBIN];   // zero-init at load; invariant: zero at kernel entry
__device__ float              g_dice[NB * 8];
__device__ unsigned int       g_sem;

__device__ __forceinline__ float tanh_fast(float x) {
    float t;
    asm("tanh.approx.f32 %0, %1;" : "=f"(t) : "f"(x));
    return t;
}

__global__ __launch_bounds__(NTH) void pan_fused(
    const float4* __restrict__ pr, const float4* __restrict__ rg,
    const float4* __restrict__ pk, const float4* __restrict__ kg,
    const float4* __restrict__ sim,
    const int4* __restrict__ tl, const int4* __restrict__ kl,
    float* __restrict__ out)
{
    __shared__ unsigned long long smh[NBIN];
    __shared__ float smd[8];
    __shared__ unsigned int s_last;
    const int b   = blockIdx.y;
    const int tid = threadIdx.x;

    if (tid < NBIN) smh[tid] = 0ull;
    if (tid < 8)    smd[tid] = 0.0f;
    __syncthreads();

    const float4* __restrict__ prb = pr + (size_t)b * HW4;
    const float4* __restrict__ rgb = rg + (size_t)b * HW4;
    const float4* __restrict__ pkb = pk + (size_t)b * HW4;
    const float4* __restrict__ kgb = kg + (size_t)b * HW4;
    const float4* __restrict__ smb = sim + (size_t)b * 4 * HW4;
    const int4*   __restrict__ tlb = tl + (size_t)b * HW4;
    const int4*   __restrict__ klb = kl + (size_t)b * HW4;

    // dice accumulators in t-space: p = 0.5*(1+t), t = tanh(x/2)
    float St_r = 0.f, St2_r = 0.f, Sgt_r = 0.f, Sg_r = 0.f;
    float St_k = 0.f, St2_k = 0.f, Sgt_k = 0.f, Sg_k = 0.f;

    for (int g = blockIdx.x * NTH + tid; g < HW4; g += BPB * NTH) {
        float4 A  = prb[g];
        float4 G  = rgb[g];
        float4 C  = pkb[g];
        float4 D  = kgb[g];
        float4 S0 = smb[g];
        float4 S1 = smb[HW4 + g];
        float4 S2 = smb[2 * HW4 + g];
        float4 S3 = smb[3 * HW4 + g];
        int4   T  = tlb[g];
        int4   K  = klb[g];

#define PAN_PROC(ax, gx, cx, dx, s0x, s1x, s2x, s3x, tx, kx) do {              \
        float t1_ = tanh_fast(0.5f * (ax));                                    \
        St_r  += t1_;                                                          \
        St2_r  = fmaf(t1_, t1_, St2_r);                                        \
        Sgt_r  = fmaf(t1_, (gx), Sgt_r);                                       \
        Sg_r  += (gx);                                                         \
        float t2_ = tanh_fast(0.5f * (cx));                                    \
        St_k  += t2_;                                                          \
        St2_k  = fmaf(t2_, t2_, St2_k);                                        \
        Sgt_k  = fmaf(t2_, (dx), Sgt_k);                                       \
        Sg_k  += (dx);                                                         \
        float s2_ = fmaf((s0x),(s0x), fmaf((s1x),(s1x),                        \
                    fmaf((s2x),(s2x), (s3x)*(s3x))));                          \
        unsigned long long v_ = __float2ull_rn(s2_ * S2_SCALE) | CNT_BIT;      \
        atomicAdd(&smh[(tx) * NSEG + (kx)], v_);                               \
    } while (0)

        PAN_PROC(A.x, G.x, C.x, D.x, S0.x, S1.x, S2.x, S3.x, T.x, K.x);
        PAN_PROC(A.y, G.y, C.y, D.y, S0.y, S1.y, S2.y, S3.y, T.y, K.y);
        PAN_PROC(A.z, G.z, C.z, D.z, S0.z, S1.z, S2.z, S3.z, T.z, K.z);
        PAN_PROC(A.w, G.w, C.w, D.w, S0.w, S1.w, S2.w, S3.w, T.w, K.w);
#undef PAN_PROC
    }

    // warp-reduce dice accumulators, one shared atomic per warp
    #pragma unroll
    for (int o = 16; o; o >>= 1) {
        St_r  += __shfl_down_sync(0xffffffffu, St_r,  o);
        St2_r += __shfl_down_sync(0xffffffffu, St2_r, o);
        Sgt_r += __shfl_down_sync(0xffffffffu, Sgt_r, o);
        Sg_r  += __shfl_down_sync(0xffffffffu, Sg_r,  o);
        St_k  += __shfl_down_sync(0xffffffffu, St_k,  o);
        St2_k += __shfl_down_sync(0xffffffffu, St2_k, o);
        Sgt_k += __shfl_down_sync(0xffffffffu, Sgt_k, o);
        Sg_k  += __shfl_down_sync(0xffffffffu, Sg_k,  o);
    }
    if ((tid & 31) == 0) {
        atomicAdd(&smd[0], St_r);  atomicAdd(&smd[1], St2_r);
        atomicAdd(&smd[2], Sgt_r); atomicAdd(&smd[3], Sg_r);
        atomicAdd(&smd[4], St_k);  atomicAdd(&smd[5], St2_k);
        atomicAdd(&smd[6], Sgt_k); atomicAdd(&smd[7], Sg_k);
    }
    __syncthreads();

    // flush block partials to global
    if (tid < NBIN) atomicAdd(&g_hist[b * NBIN + tid], smh[tid]);
    if (tid < 8)    atomicAdd(&g_dice[b * 8 + tid], smd[tid]);
    __threadfence();
    __syncthreads();
    if (tid == 0)
        s_last = (atomicAdd(&g_sem, 1u) == (unsigned)(BPB * NB - 1)) ? 1u : 0u;
    __syncthreads();
    if (!s_last) return;

    // ---------------- finalize (last block only) ----------------
    __threadfence();

    float lr = 0.f, lk = 0.f, lagg = 0.f, ldis = 0.f;
    if (tid < NB) {
        float ct[NSEG], ck[NSEG], T2[NSEG], K2[NSEG], Ssd[NSEG], a[8];
        #pragma unroll 1
        for (int i = 0; i < NSEG; i++) { ct[i]=0.f; ck[i]=0.f; T2[i]=0.f; K2[i]=0.f; Ssd[i]=0.f; }
        #pragma unroll 1
        for (int t = 0; t < NSEG; t++) {
            #pragma unroll 1
            for (int k = 0; k < NSEG; k++) {
                unsigned long long v = __ldcg(&g_hist[tid * NBIN + t * NSEG + k]);
                float cnt = (float)(v >> 40);
                float s   = (float)(v & S2_MASK) * INV_S2_SCALE;
                T2[t] += s;   K2[k] += s;
                ct[t] += cnt; ck[k] += cnt;
                if (t == k) Ssd[t] = s;
            }
        }
        float St  = __ldcg(&g_dice[tid*8+0]), St2 = __ldcg(&g_dice[tid*8+1]);
        float Sgt = __ldcg(&g_dice[tid*8+2]), Sg  = __ldcg(&g_dice[tid*8+3]);
        float I = 0.5f * (Sgt + Sg);
        float P = 0.25f * (NPXF + 2.f * St + St2);
        lr = 1.0f - (2.0f * I + EPSF) / ((P + EPSF) + (Sg + EPSF));

        St  = __ldcg(&g_dice[tid*8+4]); St2 = __ldcg(&g_dice[tid*8+5]);
        Sgt = __ldcg(&g_dice[tid*8+6]); Sg  = __ldcg(&g_dice[tid*8+7]);
        I = 0.5f * (Sgt + Sg);
        P = 0.25f * (NPXF + 2.f * St + St2);
        lk = 1.0f - (2.0f * I + EPSF) / ((P + EPSF) + (Sg + EPSF));

        #pragma unroll 1
        for (int i = 1; i < NSEG; i++) {
            float inv = 1.0f / (ck[i] + 1.0f);
            float n2  = T2[i] - (2.0f * inv - inv * inv) * Ssd[i]
                        + inv * inv * (K2[i] - Ssd[i]);
            float nrm = sqrtf(fmaxf(n2, 0.0f));
            float d   = nrm - 0.5f;                    // SIGMA_AGG (no clamp, per reference)
            lagg += logf(d * d + 1.0f) / (ct[i] + 1.0f);
            float c1 = ck[i] + 0.001f;
            a[i - 1] = K2[i] / (c1 * c1);
        }
        #pragma unroll 1
        for (int i = 0; i < 8; i++) {
            #pragma unroll 1
            for (int j = i + 1; j < 8; j++) {
                float pr_ = 3.0f - sqrtf(a[i] + a[j]); // SIGMA_DIS
                ldis += logf(pr_ * pr_ + 1.0f);
            }
        }
        ldis *= (1.0f / 56.0f);
    }

    if (tid < 32) {
        #pragma unroll
        for (int o = 16; o; o >>= 1) {
            lr   += __shfl_down_sync(0xffffffffu, lr,   o);
            lk   += __shfl_down_sync(0xffffffffu, lk,   o);
            lagg += __shfl_down_sync(0xffffffffu, lagg, o);
            ldis += __shfl_down_sync(0xffffffffu, ldis, o);
        }
        if (tid == 0) {
            out[0] = lr + 0.5f * lk + 0.25f * (lagg + ldis);  // ALPHA, BETA
            out[1] = lr;
            out[2] = lk;
            out[3] = lagg;
            out[4] = ldis;
        }
    }
    __syncthreads();

    // reset scratch for next graph replay (preserves entry invariant)
    for (int i = tid; i < NB * NBIN; i += NTH) g_hist[i] = 0ull;
    for (int i = tid; i < NB * 8;    i += NTH) g_dice[i] = 0.f;
    __threadfence();
    __syncthreads();
    if (tid == 0) g_sem = 0u;
}

extern "C" void kernel_launch(void* const* d_in, const int* in_sizes, int n_in,
                              void* d_out, int out_size) {
    (void)in_sizes; (void)n_in; (void)out_size;
    dim3 grid(BPB, NB);
    pan_fused<<<grid, NTH>>>(
        (const float4*)d_in[0], (const float4*)d_in[1],
        (const float4*)d_in[2], (const float4*)d_in[3],
        (const float4*)d_in[4],
        (const int4*)d_in[5],  (const int4*)d_in[6],
        (float*)d_out);
}